// round 1
// baseline (speedup 1.0000x reference)
#include <cuda_runtime.h>
#include <cstdint>

// MultiGridAgentEncoder: fused slot-gather + relu(x @ W + b)
// B=131072 rows, x=117 features (query 13 + 4 grey slots*13 + 4 yellow slots*13),
// W (117,256) row-major, out (B,256) fp32.
//
// Strategy: 64-row tiles. W padded to 128 K-rows in smem. x tile stored
// transposed xT[k][r] so adjacent rows form natural f32x2 packed operands.
// Compute: 8x8 register tile per thread using packed fma.rn.f32x2 (FFMA2).

#define NTHREADS 256
#define NTILES   2048   // 131072 / 64
#define TILE_R   64

__device__ __forceinline__ unsigned long long pk2(float a, float b) {
    unsigned long long r;
    asm("mov.b64 %0, {%1, %2};" : "=l"(r) : "f"(a), "f"(b));
    return r;
}
__device__ __forceinline__ void upk2(unsigned long long v, float& a, float& b) {
    asm("mov.b64 {%0, %1}, %2;" : "=f"(a), "=f"(b) : "l"(v));
}
__device__ __forceinline__ unsigned long long ffma2(unsigned long long a,
                                                    unsigned long long b,
                                                    unsigned long long c) {
    unsigned long long d;
    asm("fma.rn.f32x2 %0, %1, %2, %3;" : "=l"(d) : "l"(a), "l"(b), "l"(c));
    return d;
}

// smem layout (floats):
//   Ws   [128*256]          = 32768 floats (131072 B)
//   xT   [128*64]           =  8192 floats ( 32768 B)   xT[k][r]
//   AF   [64*16*13]         = 13312 floats ( 53248 B)   AF[r][agent][feat]
//   slotA[64*8] (int)       =   512 ints   (  2048 B)
// total = 219136 B dynamic smem
#define SMEM_BYTES 219136

__global__ __launch_bounds__(256, 1)
void mg_encoder_kernel(const float* __restrict__ qpos, const float* __restrict__ qdir,
                       const float* __restrict__ qab,  const float* __restrict__ qcar,
                       const float* __restrict__ qst,
                       const float* __restrict__ apos, const float* __restrict__ adir,
                       const float* __restrict__ aab,  const float* __restrict__ acar,
                       const float* __restrict__ ast,
                       const int*   __restrict__ color,
                       const float* __restrict__ W,    const float* __restrict__ bias,
                       float* __restrict__ out)
{
    extern __shared__ float sm[];
    float* Ws = sm;                          // 32768 floats
    float* xT = sm + 32768;                  // 8192 floats
    float* AF = sm + 32768 + 8192;           // 13312 floats
    int*   slotA = (int*)(sm + 32768 + 8192 + 13312);  // 512 ints

    const int tid = threadIdx.x;
    const int cg = tid & 31;   // col group: cols cg*4..+3 and 128+cg*4..+3
    const int rg = tid >> 5;   // row group: rows rg*8..+7

    // Load W into smem, zero-pad K rows 117..127
    for (int i = tid; i < 128 * 256; i += NTHREADS)
        Ws[i] = (i < 117 * 256) ? W[i] : 0.0f;
    // Zero-pad xT rows 117..127 once (never rewritten)
    for (int i = tid; i < 11 * 64; i += NTHREADS)
        xT[117 * 64 + i] = 0.0f;

    // Bias in registers (cols cg*4+j and 128+cg*4+j)
    float bl[4], bh[4];
#pragma unroll
    for (int j = 0; j < 4; j++) {
        bl[j] = bias[cg * 4 + j];
        bh[j] = bias[128 + cg * 4 + j];
    }
    __syncthreads();

    for (int tile = blockIdx.x; tile < NTILES; tile += gridDim.x) {
        const int row0 = tile * TILE_R;

        // ---- Phase A1: slot assignment (threads 0..63, one per row) ----
        if (tid < 64) {
            const int r = tid;
            const int4* cp = (const int4*)(color + (size_t)(row0 + r) * 16);
            int4 v0 = cp[0], v1 = cp[1], v2 = cp[2], v3 = cp[3];
            int cols[16] = { v0.x, v0.y, v0.z, v0.w,  v1.x, v1.y, v1.z, v1.w,
                             v2.x, v2.y, v2.z, v2.w,  v3.x, v3.y, v3.z, v3.w };
            int sa[8];
#pragma unroll
            for (int s = 0; s < 8; s++) sa[s] = -1;
            int sg = 0, sy = 0;
#pragma unroll
            for (int n = 0; n < 16; n++) {
                int c = cols[n];
                if (c == 5) { if (sg < 4) sa[sg] = n; sg++; }       // grey -> slots 0..3
                else if (c == 4) { if (sy < 4) sa[4 + sy] = n; sy++; } // yellow -> 4..7
            }
#pragma unroll
            for (int s = 0; s < 8; s++) slotA[r * 8 + s] = sa[s];
        }

        // ---- Phase A1: coalesced staging of all agent features -> AF[r][n][f] ----
        {
            const float* src = apos + (size_t)row0 * 32;
            for (int i = tid; i < 2048; i += NTHREADS) {
                int r = i >> 5, j = i & 31;
                AF[r * 208 + (j >> 1) * 13 + (j & 1)] = src[i];
            }
        }
        {
            const float* src = adir + (size_t)row0 * 64;
            for (int i = tid; i < 4096; i += NTHREADS) {
                int r = i >> 6, j = i & 63;
                AF[r * 208 + (j >> 2) * 13 + 2 + (j & 3)] = src[i];
            }
        }
        {
            const float* src = aab + (size_t)row0 * 32;
            for (int i = tid; i < 2048; i += NTHREADS) {
                int r = i >> 5, j = i & 31;
                AF[r * 208 + (j >> 1) * 13 + 6 + (j & 1)] = src[i];
            }
        }
        {
            const float* src = acar + (size_t)row0 * 32;
            for (int i = tid; i < 2048; i += NTHREADS) {
                int r = i >> 5, j = i & 31;
                AF[r * 208 + (j >> 1) * 13 + 8 + (j & 1)] = src[i];
            }
        }
        {
            const float* src = ast + (size_t)row0 * 48;
            for (int i = tid; i < 3072; i += NTHREADS) {
                int r = i / 48, j = i - r * 48;
                AF[r * 208 + (j / 3) * 13 + 10 + (j % 3)] = src[i];
            }
        }

        // ---- Phase A1: query features -> xT rows 0..12 ----
        for (int i = tid; i < 64 * 13; i += NTHREADS) {
            int r = i & 63, k = i >> 6;
            int brow = row0 + r;
            float v;
            if (k < 2)       v = qpos[brow * 2 + k];
            else if (k < 6)  v = qdir[brow * 4 + (k - 2)];
            else if (k < 8)  v = qab [brow * 2 + (k - 6)];
            else if (k < 10) v = qcar[brow * 2 + (k - 8)];
            else             v = qst [brow * 3 + (k - 10)];
            xT[k * 64 + r] = v;
        }
        __syncthreads();

        // ---- Phase A2: scatter AF -> xT rows 13..116 via slotA ----
        for (int i = tid; i < 64 * 104; i += NTHREADS) {
            int r = i & 63, j = i >> 6;          // j in 0..103
            int s = j / 13, f = j - s * 13;      // slot, feature
            int a = slotA[r * 8 + s];
            xT[(13 + j) * 64 + r] = (a >= 0) ? AF[r * 208 + a * 13 + f] : 0.0f;
        }
        __syncthreads();

        // ---- GEMM: 8 rows x 8 cols per thread, packed f32x2 FMA ----
        unsigned long long acc[4][8];
#pragma unroll
        for (int p = 0; p < 4; p++)
#pragma unroll
            for (int j = 0; j < 8; j++) acc[p][j] = 0ULL;

        const float* xb = xT + rg * 8;
        const float* wb = Ws + cg * 4;

#pragma unroll 4
        for (int k = 0; k < 128; k++) {
            // x pairs for rows rg*8..+7 (warp-broadcast LDS.128)
            const ulonglong2 xa = *(const ulonglong2*)(xb + k * 64);
            const ulonglong2 xc = *(const ulonglong2*)(xb + k * 64 + 4);
            // W for cols cg*4..+3 and 128+cg*4..+3 (conflict-free LDS.128)
            const float4 wlo = *(const float4*)(wb + k * 256);
            const float4 whi = *(const float4*)(wb + k * 256 + 128);

            unsigned long long xp[4] = { xa.x, xa.y, xc.x, xc.y };
            unsigned long long wd[8] = {
                pk2(wlo.x, wlo.x), pk2(wlo.y, wlo.y), pk2(wlo.z, wlo.z), pk2(wlo.w, wlo.w),
                pk2(whi.x, whi.x), pk2(whi.y, whi.y), pk2(whi.z, whi.z), pk2(whi.w, whi.w)
            };
#pragma unroll
            for (int p = 0; p < 4; p++)
#pragma unroll
                for (int j = 0; j < 8; j++)
                    acc[p][j] = ffma2(xp[p], wd[j], acc[p][j]);
        }

        // ---- Epilogue: bias + relu + coalesced float4 stores ----
#pragma unroll
        for (int p = 0; p < 4; p++) {
            const int r = row0 + rg * 8 + p * 2;   // rows r, r+1
            float lo[8], hi[8];
#pragma unroll
            for (int j = 0; j < 8; j++) upk2(acc[p][j], lo[j], hi[j]);

            float4 o0 = make_float4(fmaxf(lo[0] + bl[0], 0.0f), fmaxf(lo[1] + bl[1], 0.0f),
                                    fmaxf(lo[2] + bl[2], 0.0f), fmaxf(lo[3] + bl[3], 0.0f));
            float4 o1 = make_float4(fmaxf(hi[0] + bl[0], 0.0f), fmaxf(hi[1] + bl[1], 0.0f),
                                    fmaxf(hi[2] + bl[2], 0.0f), fmaxf(hi[3] + bl[3], 0.0f));
            float4 o2 = make_float4(fmaxf(lo[4] + bh[0], 0.0f), fmaxf(lo[5] + bh[1], 0.0f),
                                    fmaxf(lo[6] + bh[2], 0.0f), fmaxf(lo[7] + bh[3], 0.0f));
            float4 o3 = make_float4(fmaxf(hi[4] + bh[0], 0.0f), fmaxf(hi[5] + bh[1], 0.0f),
                                    fmaxf(hi[6] + bh[2], 0.0f), fmaxf(hi[7] + bh[3], 0.0f));

            *(float4*)(out + (size_t)r * 256 + cg * 4)             = o0;
            *(float4*)(out + (size_t)(r + 1) * 256 + cg * 4)       = o1;
            *(float4*)(out + (size_t)r * 256 + 128 + cg * 4)       = o2;
            *(float4*)(out + (size_t)(r + 1) * 256 + 128 + cg * 4) = o3;
        }
        __syncthreads();   // protect xT/AF/slotA before next tile's writes
    }
}

extern "C" void kernel_launch(void* const* d_in, const int* in_sizes, int n_in,
                              void* d_out, int out_size)
{
    const float* qpos  = (const float*)d_in[0];
    const float* qdir  = (const float*)d_in[1];
    const float* qab   = (const float*)d_in[2];
    const float* qcar  = (const float*)d_in[3];
    const float* qst   = (const float*)d_in[4];
    const float* apos  = (const float*)d_in[5];
    const float* adir  = (const float*)d_in[6];
    const float* aab   = (const float*)d_in[7];
    const float* acar  = (const float*)d_in[8];
    const float* ast   = (const float*)d_in[9];
    const int*   color = (const int*)  d_in[10];
    const float* W     = (const float*)d_in[11];
    const float* bias  = (const float*)d_in[12];
    float* out = (float*)d_out;

    cudaFuncSetAttribute(mg_encoder_kernel,
                         cudaFuncAttributeMaxDynamicSharedMemorySize, SMEM_BYTES);

    mg_encoder_kernel<<<512, NTHREADS, SMEM_BYTES>>>(
        qpos, qdir, qab, qcar, qst,
        apos, adir, aab, acar, ast,
        color, W, bias, out);
}

// round 3
// speedup vs baseline: 2.0726x; 2.0726x over previous
#include <cuda_runtime.h>
#include <cuda_bf16.h>
#include <cstdint>

// MultiGridAgentEncoder: fused slot-gather + relu(x @ W + b)
// bf16 split-precision GEMM via mma.sync.m16n8k16 (HMMA), fp32 accum.
// Per CTA: M=128 rows, N=256 cols, K=117 padded to 128. 512 threads, 16 warps (4x4).
// x = x_hi + x_lo, W = W_hi + W_lo; acc = AH*BH + AH*BL + AL*BH.

#define NTHREADS 512
#define PITCH_B  272          // bytes per K-row (128 bf16 = 256B + 16B pad), conflict-free

// smem byte offsets
#define SM_A_HI  0            // 128 * 272 = 34816
#define SM_A_LO  34816
#define SM_B_HI  69632        // 256 * 272 = 69632
#define SM_B_LO  139264
#define SM_SLOT  208896       // 128 rows * 8 ints = 4096
#define SM_BIAS  212992       // 256 floats = 1024
#define SMEM_BYTES 214016

static __device__ __forceinline__ uint32_t smem_u32(const void* p) {
    uint32_t a;
    asm("{ .reg .u64 t; cvta.to.shared.u64 t, %1; cvt.u32.u64 %0, t; }" : "=r"(a) : "l"(p));
    return a;
}
static __device__ __forceinline__ void ldsm_x4(uint32_t& r0, uint32_t& r1, uint32_t& r2,
                                               uint32_t& r3, uint32_t addr) {
    asm volatile("ldmatrix.sync.aligned.m8n8.x4.shared.b16 {%0,%1,%2,%3}, [%4];"
                 : "=r"(r0), "=r"(r1), "=r"(r2), "=r"(r3) : "r"(addr));
}
static __device__ __forceinline__ void mma_bf16(float* c, const uint32_t* a,
                                                uint32_t b0, uint32_t b1) {
    asm volatile(
        "mma.sync.aligned.m16n8k16.row.col.f32.bf16.bf16.f32 "
        "{%0,%1,%2,%3}, {%4,%5,%6,%7}, {%8,%9}, {%0,%1,%2,%3};"
        : "+f"(c[0]), "+f"(c[1]), "+f"(c[2]), "+f"(c[3])
        : "r"(a[0]), "r"(a[1]), "r"(a[2]), "r"(a[3]), "r"(b0), "r"(b1));
}

__global__ __launch_bounds__(512, 1)
void mg_enc_hmma(const float* __restrict__ qpos, const float* __restrict__ qdir,
                 const float* __restrict__ qab,  const float* __restrict__ qcar,
                 const float* __restrict__ qst,
                 const float* __restrict__ apos, const float* __restrict__ adir,
                 const float* __restrict__ aab,  const float* __restrict__ acar,
                 const float* __restrict__ ast,
                 const int*   __restrict__ color,
                 const float* __restrict__ W,    const float* __restrict__ bias,
                 float* __restrict__ out)
{
    extern __shared__ __align__(128) char smem[];
    const uint32_t sbase = smem_u32(smem);
    const int tid = threadIdx.x;
    const int wid = tid >> 5, lid = tid & 31;
    const int row0 = blockIdx.x * 128;

    // bias -> smem
    if (tid < 256) ((float*)(smem + SM_BIAS))[tid] = bias[tid];

    // ---- slot assignment: thread m handles row row0+m ----
    if (tid < 128) {
        const int4* cp = (const int4*)(color + (size_t)(row0 + tid) * 16);
        int4 v0 = cp[0], v1 = cp[1], v2 = cp[2], v3 = cp[3];
        int cols[16] = { v0.x, v0.y, v0.z, v0.w, v1.x, v1.y, v1.z, v1.w,
                         v2.x, v2.y, v2.z, v2.w, v3.x, v3.y, v3.z, v3.w };
        int sa[8];
#pragma unroll
        for (int s = 0; s < 8; s++) sa[s] = -1;
        int sg = 0, sy = 0;
#pragma unroll
        for (int n = 0; n < 16; n++) {
            int c = cols[n];
            if (c == 5) { if (sg < 4) sa[sg] = n; sg++; }          // grey -> slots 0..3
            else if (c == 4) { if (sy < 4) sa[4 + sy] = n; sy++; } // yellow -> slots 4..7
        }
        int* sl = (int*)(smem + SM_SLOT) + tid * 8;
#pragma unroll
        for (int s = 0; s < 8; s++) sl[s] = sa[s];
    }

    // ---- B fill: B[n][k] K-major, split bf16. 2 threads per col (k halves) ----
    {
        const int n = tid & 255;
        const int half = tid >> 8;            // 0: k 0..63, 1: k 64..127
        char* bh = smem + SM_B_HI + n * PITCH_B;
        char* bl = smem + SM_B_LO + n * PITCH_B;
#pragma unroll
        for (int ku = 0; ku < 8; ku++) {
            const int kk = half * 64 + ku * 8;
            __nv_bfloat16 hb[8], lb[8];
#pragma unroll
            for (int j = 0; j < 8; j++) {
                int k = kk + j;
                float w = (k < 117) ? W[k * 256 + n] : 0.0f;
                __nv_bfloat16 h = __float2bfloat16(w);
                hb[j] = h;
                lb[j] = __float2bfloat16(w - __bfloat162float(h));
            }
            *(uint4*)(bh + kk * 2) = *(const uint4*)hb;
            *(uint4*)(bl + kk * 2) = *(const uint4*)lb;
        }
    }

    // ---- A fill: A[m][k] K-major, split bf16. Gather via slot table ----
    {
        const int m = tid & 127;
        const int q = tid >> 7;               // 0..3
        const int row = row0 + m;
        const int* sl = (const int*)(smem + SM_SLOT) + m * 8;
        char* ah = smem + SM_A_HI + m * PITCH_B;
        char* al = smem + SM_A_LO + m * PITCH_B;
        __syncthreads();                       // slot table ready (also covers bias)
#pragma unroll
        for (int it = 0; it < 4; it++) {
            const int ku = q + 4 * it;        // 0..15
            float x[8];
#pragma unroll
            for (int j = 0; j < 8; j++) {
                const int k = ku * 8 + j;
                float v = 0.0f;
                if (k < 13) {
                    if (k < 2)       v = qpos[row * 2 + k];
                    else if (k < 6)  v = qdir[row * 4 + (k - 2)];
                    else if (k < 8)  v = qab [row * 2 + (k - 6)];
                    else if (k < 10) v = qcar[row * 2 + (k - 8)];
                    else             v = qst [row * 3 + (k - 10)];
                } else if (k < 117) {
                    const int t = k - 13;
                    const int s = t / 13, f = t - s * 13;
                    const int a = sl[s];
                    if (a >= 0) {
                        const int base = row * 16 + a;
                        if (f < 2)       v = apos[base * 2 + f];
                        else if (f < 6)  v = adir[base * 4 + (f - 2)];
                        else if (f < 8)  v = aab [base * 2 + (f - 6)];
                        else if (f < 10) v = acar[base * 2 + (f - 8)];
                        else             v = ast [base * 3 + (f - 10)];
                    }
                }
                x[j] = v;
            }
            __nv_bfloat16 hb[8], lb[8];
#pragma unroll
            for (int j = 0; j < 8; j++) {
                __nv_bfloat16 h = __float2bfloat16(x[j]);
                hb[j] = h;
                lb[j] = __float2bfloat16(x[j] - __bfloat162float(h));
            }
            *(uint4*)(ah + ku * 16) = *(const uint4*)hb;
            *(uint4*)(al + ku * 16) = *(const uint4*)lb;
        }
    }
    __syncthreads();

    // ---- MMA: warp (4x4) tile 32x64, acc[2][8][4] ----
    const int warp_m = wid >> 2, warp_n = wid & 3;
    float acc[2][8][4];
#pragma unroll
    for (int mt = 0; mt < 2; mt++)
#pragma unroll
        for (int nt = 0; nt < 8; nt++)
#pragma unroll
            for (int e = 0; e < 4; e++) acc[mt][nt][e] = 0.0f;

    // per-lane ldmatrix base offsets (row = lid%16, col-half = lid/16)
    const uint32_t lrow = lid & 15, lhalf = (uint32_t)lid >> 4;
    const uint32_t a_lane = (warp_m * 32 + lrow) * PITCH_B + lhalf * 16;
    const uint32_t b_lane = (warp_n * 64 + lrow) * PITCH_B + lhalf * 16;

    const uint32_t passA[3] = { sbase + SM_A_HI, sbase + SM_A_HI, sbase + SM_A_LO };
    const uint32_t passB[3] = { sbase + SM_B_HI, sbase + SM_B_LO, sbase + SM_B_HI };

    for (int pass = 0; pass < 3; pass++) {
        const uint32_t Ab = passA[pass] + a_lane;
        const uint32_t Bb = passB[pass] + b_lane;
#pragma unroll 4
        for (int ks = 0; ks < 8; ks++) {
            const uint32_t koff = ks * 32;    // 16 k * 2B
            uint32_t a[2][4];
#pragma unroll
            for (int mt = 0; mt < 2; mt++)
                ldsm_x4(a[mt][0], a[mt][1], a[mt][2], a[mt][3],
                        Ab + mt * (16 * PITCH_B) + koff);
            uint32_t b[4][4];
#pragma unroll
            for (int nb = 0; nb < 4; nb++)
                ldsm_x4(b[nb][0], b[nb][1], b[nb][2], b[nb][3],
                        Bb + nb * (16 * PITCH_B) + koff);
#pragma unroll
            for (int mt = 0; mt < 2; mt++)
#pragma unroll
                for (int nb = 0; nb < 4; nb++) {
                    mma_bf16(acc[mt][nb * 2 + 0], a[mt], b[nb][0], b[nb][2]);
                    mma_bf16(acc[mt][nb * 2 + 1], a[mt], b[nb][1], b[nb][3]);
                }
        }
    }

    // ---- epilogue: bias + relu + direct stores (full 32B sectors) ----
    const float* biass = (const float*)(smem + SM_BIAS);
    const int rbase = row0 + warp_m * 32 + (lid >> 2);
    const int cbase = warp_n * 64 + (lid & 3) * 2;
#pragma unroll
    for (int mt = 0; mt < 2; mt++) {
#pragma unroll
        for (int nt = 0; nt < 8; nt++) {
            const int c = cbase + nt * 8;
            const float b0 = biass[c], b1 = biass[c + 1];
            float2 v0, v1;
            v0.x = fmaxf(acc[mt][nt][0] + b0, 0.0f);
            v0.y = fmaxf(acc[mt][nt][1] + b1, 0.0f);
            v1.x = fmaxf(acc[mt][nt][2] + b0, 0.0f);
            v1.y = fmaxf(acc[mt][nt][3] + b1, 0.0f);
            const size_t r0 = (size_t)(rbase + mt * 16);
            *(float2*)(out + r0 * 256 + c)       = v0;
            *(float2*)(out + (r0 + 8) * 256 + c) = v1;
        }
    }
}

extern "C" void kernel_launch(void* const* d_in, const int* in_sizes, int n_in,
                              void* d_out, int out_size)
{
    const float* qpos  = (const float*)d_in[0];
    const float* qdir  = (const float*)d_in[1];
    const float* qab   = (const float*)d_in[2];
    const float* qcar  = (const float*)d_in[3];
    const float* qst   = (const float*)d_in[4];
    const float* apos  = (const float*)d_in[5];
    const float* adir  = (const float*)d_in[6];
    const float* aab   = (const float*)d_in[7];
    const float* acar  = (const float*)d_in[8];
    const float* ast   = (const float*)d_in[9];
    const int*   color = (const int*)  d_in[10];
    const float* W     = (const float*)d_in[11];
    const float* bias  = (const float*)d_in[12];
    float* out = (float*)d_out;

    cudaFuncSetAttribute(mg_enc_hmma,
                         cudaFuncAttributeMaxDynamicSharedMemorySize, SMEM_BYTES);

    mg_enc_hmma<<<1024, NTHREADS, SMEM_BYTES>>>(
        qpos, qdir, qab, qcar, qst,
        apos, adir, aab, acar, ast,
        color, W, bias, out);
}

// round 4
// speedup vs baseline: 2.5152x; 1.2136x over previous
#include <cuda_runtime.h>
#include <cuda_bf16.h>
#include <cstdint>

// MultiGridAgentEncoder: fused slot-gather + relu(x @ W + b)
// bf16 split-precision GEMM via mma.sync.m16n8k16 (HMMA), fp32 accum.
// R4: smem-staged gather (coalesced global -> AF -> scatter), pre-split W.

#define NTHREADS 512
#define PITCH_B  272          // bytes per K-row (128 bf16 + 16B pad), ldmatrix conflict-free
#define AF_PITCH 209          // floats per row in AF staging buffer

// smem byte offsets
#define SM_A_HI  0            // 128 * 272 = 34816
#define SM_A_LO  34816        // ends 69632
#define SM_B_HI  69632        // 256 * 272 = 69632, ends 139264
#define SM_B_LO  139264       // ends 208896
#define SM_AF    69632        // AF: 128 * 209 * 4 = 107008, ends 176640 (inside B region, used pre-B)
#define SM_SLOT  208896       // [s][r]: 8 * 128 ints = 4096
#define SM_BIAS  212992       // 256 floats
#define SMEM_BYTES 214016

// Pre-split W (filled once by w_split kernel): [n][k] bf16, k padded to 128
__device__ __nv_bfloat16 g_Whi[256 * 128];
__device__ __nv_bfloat16 g_Wlo[256 * 128];

__global__ void w_split(const float* __restrict__ W) {
    const int k = blockIdx.x;        // 0..127
    const int n = threadIdx.x;       // 0..255
    float w = (k < 117) ? W[k * 256 + n] : 0.0f;
    __nv_bfloat16 h = __float2bfloat16(w);
    g_Whi[n * 128 + k] = h;
    g_Wlo[n * 128 + k] = __float2bfloat16(w - __bfloat162float(h));
}

static __device__ __forceinline__ uint32_t smem_u32(const void* p) {
    uint32_t a;
    asm("{ .reg .u64 t; cvta.to.shared.u64 t, %1; cvt.u32.u64 %0, t; }" : "=r"(a) : "l"(p));
    return a;
}
static __device__ __forceinline__ void ldsm_x4(uint32_t& r0, uint32_t& r1, uint32_t& r2,
                                               uint32_t& r3, uint32_t addr) {
    asm volatile("ldmatrix.sync.aligned.m8n8.x4.shared.b16 {%0,%1,%2,%3}, [%4];"
                 : "=r"(r0), "=r"(r1), "=r"(r2), "=r"(r3) : "r"(addr));
}
static __device__ __forceinline__ void mma_bf16(float* c, const uint32_t* a,
                                                uint32_t b0, uint32_t b1) {
    asm volatile(
        "mma.sync.aligned.m16n8k16.row.col.f32.bf16.bf16.f32 "
        "{%0,%1,%2,%3}, {%4,%5,%6,%7}, {%8,%9}, {%0,%1,%2,%3};"
        : "+f"(c[0]), "+f"(c[1]), "+f"(c[2]), "+f"(c[3])
        : "r"(a[0]), "r"(a[1]), "r"(a[2]), "r"(a[3]), "r"(b0), "r"(b1));
}
static __device__ __forceinline__ void splitw(float v, __nv_bfloat16& h, __nv_bfloat16& l) {
    h = __float2bfloat16(v);
    l = __float2bfloat16(v - __bfloat162float(h));
}

__global__ __launch_bounds__(512, 1)
void mg_enc_hmma(const float* __restrict__ qpos, const float* __restrict__ qdir,
                 const float* __restrict__ qab,  const float* __restrict__ qcar,
                 const float* __restrict__ qst,
                 const float* __restrict__ apos, const float* __restrict__ adir,
                 const float* __restrict__ aab,  const float* __restrict__ acar,
                 const float* __restrict__ ast,
                 const int*   __restrict__ color,
                 const float* __restrict__ bias,
                 float* __restrict__ out)
{
    extern __shared__ __align__(128) char smem[];
    const uint32_t sbase = smem_u32(smem);
    const int tid = threadIdx.x;
    const int wid = tid >> 5, lid = tid & 31;
    const int row0 = blockIdx.x * 128;

    // ================= Phase 1: slots + coalesced AF stage + query + bias =================
    if (tid < 256) ((float*)(smem + SM_BIAS))[tid] = bias[tid];

    // slot assignment: thread m handles row row0+m; table layout [s][r]
    if (tid < 128) {
        const int4* cp = (const int4*)(color + (size_t)(row0 + tid) * 16);
        int4 v0 = cp[0], v1 = cp[1], v2 = cp[2], v3 = cp[3];
        int cols[16] = { v0.x, v0.y, v0.z, v0.w, v1.x, v1.y, v1.z, v1.w,
                         v2.x, v2.y, v2.z, v2.w, v3.x, v3.y, v3.z, v3.w };
        int sa[8];
#pragma unroll
        for (int s = 0; s < 8; s++) sa[s] = -1;
        int sg = 0, sy = 0;
#pragma unroll
        for (int n = 0; n < 16; n++) {
            int c = cols[n];
            if (c == 5) { if (sg < 4) sa[sg] = n; sg++; }          // grey -> slots 0..3
            else if (c == 4) { if (sy < 4) sa[4 + sy] = n; sy++; } // yellow -> slots 4..7
        }
        int* sl = (int*)(smem + SM_SLOT);
#pragma unroll
        for (int s = 0; s < 8; s++) sl[s * 128 + tid] = sa[s];
    }

    // AF stage: 4 threads per row, coalesced float4 loads, scalar smem scatter
    {
        const int r = tid >> 2, p = tid & 3;          // r: 0..127, p: 0..3
        const size_t grow = (size_t)(row0 + r);
        float* af = (float*)(smem + SM_AF) + r * AF_PITCH;
        const int a0 = 4 * p;
        // apos: 2 floats/agent -> floats p*8..p*8+7 = agents 4p..4p+3
        {
            const float4* s4 = (const float4*)(apos + grow * 32) + p * 2;
            float4 u = s4[0], v = s4[1];
            af[(a0+0)*13+0]=u.x; af[(a0+0)*13+1]=u.y; af[(a0+1)*13+0]=u.z; af[(a0+1)*13+1]=u.w;
            af[(a0+2)*13+0]=v.x; af[(a0+2)*13+1]=v.y; af[(a0+3)*13+0]=v.z; af[(a0+3)*13+1]=v.w;
        }
        // adir: 4 floats/agent -> f4 i = agent 4p+i, feats 2..5
        {
            const float4* s4 = (const float4*)(adir + grow * 64) + p * 4;
#pragma unroll
            for (int i = 0; i < 4; i++) {
                float4 u = s4[i];
                float* d = af + (a0 + i) * 13 + 2;
                d[0]=u.x; d[1]=u.y; d[2]=u.z; d[3]=u.w;
            }
        }
        // aab: feats 6,7
        {
            const float4* s4 = (const float4*)(aab + grow * 32) + p * 2;
            float4 u = s4[0], v = s4[1];
            af[(a0+0)*13+6]=u.x; af[(a0+0)*13+7]=u.y; af[(a0+1)*13+6]=u.z; af[(a0+1)*13+7]=u.w;
            af[(a0+2)*13+6]=v.x; af[(a0+2)*13+7]=v.y; af[(a0+3)*13+6]=v.z; af[(a0+3)*13+7]=v.w;
        }
        // acar: feats 8,9
        {
            const float4* s4 = (const float4*)(acar + grow * 32) + p * 2;
            float4 u = s4[0], v = s4[1];
            af[(a0+0)*13+8]=u.x; af[(a0+0)*13+9]=u.y; af[(a0+1)*13+8]=u.z; af[(a0+1)*13+9]=u.w;
            af[(a0+2)*13+8]=v.x; af[(a0+2)*13+9]=v.y; af[(a0+3)*13+8]=v.z; af[(a0+3)*13+9]=v.w;
        }
        // ast: 3 floats/agent -> floats p*12..p*12+11 = agents 4p..4p+3, feats 10..12
        {
            const float4* s4 = (const float4*)(ast + grow * 48) + p * 3;
            float t[12];
            *(float4*)(t + 0) = s4[0];
            *(float4*)(t + 4) = s4[1];
            *(float4*)(t + 8) = s4[2];
#pragma unroll
            for (int i = 0; i < 12; i++)
                af[(a0 + i / 3) * 13 + 10 + (i % 3)] = t[i];
        }
    }

    // query features -> A rows k=0..12 (thread t handles row t)
    if (tid < 128) {
        const size_t row = (size_t)(row0 + tid);
        float q[13];
        *(float2*)(q + 0) = *(const float2*)(qpos + row * 2);
        *(float4*)(q + 2) = *(const float4*)(qdir + row * 4);
        *(float2*)(q + 6) = *(const float2*)(qab  + row * 2);
        *(float2*)(q + 8) = *(const float2*)(qcar + row * 2);
        q[10] = qst[row * 3 + 0]; q[11] = qst[row * 3 + 1]; q[12] = qst[row * 3 + 2];
        char* ah = smem + SM_A_HI + tid * PITCH_B;
        char* al = smem + SM_A_LO + tid * PITCH_B;
#pragma unroll
        for (int k = 0; k < 13; k++) {
            __nv_bfloat16 h, l; splitw(q[k], h, l);
            *(__nv_bfloat16*)(ah + k * 2) = h;
            *(__nv_bfloat16*)(al + k * 2) = l;
        }
        // K-pad rows 117..127 -> zero
#pragma unroll
        for (int k = 117; k < 128; k++) {
            *(__nv_bfloat16*)(ah + k * 2) = __nv_bfloat16(0.0f);
            *(__nv_bfloat16*)(al + k * 2) = __nv_bfloat16(0.0f);
        }
    }
    __syncthreads();

    // ================= Phase 2: scatter AF -> A tiles (k=13..116) =================
    {
        const int r = tid & 127;
        const int jb = tid >> 7;                              // 0..3
        const int* sl = (const int*)(smem + SM_SLOT);
        const float* af = (const float*)(smem + SM_AF) + r * AF_PITCH;
        char* ah = smem + SM_A_HI + r * PITCH_B;
        char* al = smem + SM_A_LO + r * PITCH_B;
#pragma unroll
        for (int it = 0; it < 26; it++) {
            const int j = it * 4 + jb;                        // 0..103
            const int s = j / 13, f = j - s * 13;             // const-div -> mulshift
            const int a = sl[s * 128 + r];                    // conflict-free LDS
            const float v = (a >= 0) ? af[a * 13 + f] : 0.0f;
            __nv_bfloat16 h, l; splitw(v, h, l);
            *(__nv_bfloat16*)(ah + (13 + j) * 2) = h;
            *(__nv_bfloat16*)(al + (13 + j) * 2) = l;
        }
    }
    __syncthreads();

    // ================= Phase 3: B copy (pre-split bf16, coalesced uint4) =================
    {
        const uint4* WH = (const uint4*)g_Whi;   // [256][16]
        const uint4* WL = (const uint4*)g_Wlo;
#pragma unroll
        for (int it = 0; it < 8; it++) {
            const int idx = it * 512 + tid;
            const int n = idx >> 4, c = idx & 15;
            *(uint4*)(smem + SM_B_HI + n * PITCH_B + c * 16) = WH[n * 16 + c];
            *(uint4*)(smem + SM_B_LO + n * PITCH_B + c * 16) = WL[n * 16 + c];
        }
    }
    __syncthreads();

    // ================= Phase 4: MMA (warp 4x4 grid, warp tile 32x64) =================
    const int warp_m = wid >> 2, warp_n = wid & 3;
    float acc[2][8][4];
#pragma unroll
    for (int mt = 0; mt < 2; mt++)
#pragma unroll
        for (int nt = 0; nt < 8; nt++)
#pragma unroll
            for (int e = 0; e < 4; e++) acc[mt][nt][e] = 0.0f;

    const uint32_t lrow = lid & 15, lhalf = (uint32_t)lid >> 4;
    const uint32_t a_lane = (warp_m * 32 + lrow) * PITCH_B + lhalf * 16;
    const uint32_t b_lane = (warp_n * 64 + lrow) * PITCH_B + lhalf * 16;

    const uint32_t passA[3] = { sbase + SM_A_HI, sbase + SM_A_HI, sbase + SM_A_LO };
    const uint32_t passB[3] = { sbase + SM_B_HI, sbase + SM_B_LO, sbase + SM_B_HI };

    for (int pass = 0; pass < 3; pass++) {
        const uint32_t Ab = passA[pass] + a_lane;
        const uint32_t Bb = passB[pass] + b_lane;
#pragma unroll 4
        for (int ks = 0; ks < 8; ks++) {
            const uint32_t koff = ks * 32;
            uint32_t a[2][4];
#pragma unroll
            for (int mt = 0; mt < 2; mt++)
                ldsm_x4(a[mt][0], a[mt][1], a[mt][2], a[mt][3],
                        Ab + mt * (16 * PITCH_B) + koff);
            uint32_t b[4][4];
#pragma unroll
            for (int nb = 0; nb < 4; nb++)
                ldsm_x4(b[nb][0], b[nb][1], b[nb][2], b[nb][3],
                        Bb + nb * (16 * PITCH_B) + koff);
#pragma unroll
            for (int mt = 0; mt < 2; mt++)
#pragma unroll
                for (int nb = 0; nb < 4; nb++) {
                    mma_bf16(acc[mt][nb * 2 + 0], a[mt], b[nb][0], b[nb][2]);
                    mma_bf16(acc[mt][nb * 2 + 1], a[mt], b[nb][1], b[nb][3]);
                }
        }
    }

    // ================= Epilogue: bias + relu + direct stores =================
    const float* biass = (const float*)(smem + SM_BIAS);
    const int rbase = row0 + warp_m * 32 + (lid >> 2);
    const int cbase = warp_n * 64 + (lid & 3) * 2;
#pragma unroll
    for (int mt = 0; mt < 2; mt++) {
#pragma unroll
        for (int nt = 0; nt < 8; nt++) {
            const int c = cbase + nt * 8;
            const float b0 = biass[c], b1 = biass[c + 1];
            float2 v0, v1;
            v0.x = fmaxf(acc[mt][nt][0] + b0, 0.0f);
            v0.y = fmaxf(acc[mt][nt][1] + b1, 0.0f);
            v1.x = fmaxf(acc[mt][nt][2] + b0, 0.0f);
            v1.y = fmaxf(acc[mt][nt][3] + b1, 0.0f);
            const size_t r0 = (size_t)(rbase + mt * 16);
            *(float2*)(out + r0 * 256 + c)       = v0;
            *(float2*)(out + (r0 + 8) * 256 + c) = v1;
        }
    }
}

extern "C" void kernel_launch(void* const* d_in, const int* in_sizes, int n_in,
                              void* d_out, int out_size)
{
    const float* qpos  = (const float*)d_in[0];
    const float* qdir  = (const float*)d_in[1];
    const float* qab   = (const float*)d_in[2];
    const float* qcar  = (const float*)d_in[3];
    const float* qst   = (const float*)d_in[4];
    const float* apos  = (const float*)d_in[5];
    const float* adir  = (const float*)d_in[6];
    const float* aab   = (const float*)d_in[7];
    const float* acar  = (const float*)d_in[8];
    const float* ast   = (const float*)d_in[9];
    const int*   color = (const int*)  d_in[10];
    const float* W     = (const float*)d_in[11];
    const float* bias  = (const float*)d_in[12];
    float* out = (float*)d_out;

    w_split<<<128, 256>>>(W);

    cudaFuncSetAttribute(mg_enc_hmma,
                         cudaFuncAttributeMaxDynamicSharedMemorySize, SMEM_BYTES);
    mg_enc_hmma<<<1024, NTHREADS, SMEM_BYTES>>>(
        qpos, qdir, qab, qcar, qst,
        apos, adir, aab, acar, ast,
        color, bias, out);
}